// round 2
// baseline (speedup 1.0000x reference)
#include <cuda_runtime.h>
#include <cuda_bf16.h>
#include <cstdint>

#define M_NODES 100000
#define CH      128
#define NE      1600000

// ---------------- scratch (device globals: allocation-free) ----------------
__device__ __align__(16) float g_aggr[M_NODES * CH];   // (1+eps)*x + scatter sum
__device__ __align__(16) float g_h[M_NODES * CH];      // h = aggr @ W1^T + b1 (pre-BN)
__device__ float g_sum[CH];
__device__ float g_sumsq[CH];
__device__ float g_scale[CH];
__device__ float g_shift[CH];
__device__ int   g_i64flag;   // 1 if edge_index stored as int64, 0 if int32

// ---------------- f32x2 helpers (Blackwell packed fp32) ----------------
__device__ __forceinline__ unsigned long long pack2(float a) {
    unsigned long long r;
    asm("mov.b64 %0, {%1,%1};" : "=l"(r) : "f"(a));
    return r;
}
__device__ __forceinline__ void fma2(unsigned long long& d, unsigned long long a,
                                     unsigned long long b) {
    asm volatile("fma.rn.f32x2 %0, %1, %2, %0;" : "+l"(d) : "l"(a), "l"(b));
}
__device__ __forceinline__ void unpack2(unsigned long long v, float& lo, float& hi) {
    asm("mov.b64 {%0,%1}, %2;" : "=f"(lo), "=f"(hi) : "l"(v));
}

// ---------------- kernel 0: detect edge_index storage dtype ----------------
// If buffer holds int64 values < 2^31 (little-endian), every odd 32-bit word
// is zero. If it holds int32 node IDs, odd words are random in [0, 100000).
__global__ void detect_kernel(const int* __restrict__ ei32) {
    __shared__ int nz;
    if (threadIdx.x == 0) nz = 0;
    __syncthreads();
    for (int i = threadIdx.x; i < 4096; i += blockDim.x) {
        if (ei32[2 * i + 1] != 0) nz = 1;   // benign race: any write sets it
    }
    __syncthreads();
    if (threadIdx.x == 0) g_i64flag = (nz == 0) ? 1 : 0;
}

// ---------------- kernel 1: aggr = (1+eps)*x ; zero stats ----------------
__global__ void init_kernel(const float* __restrict__ x, const float* __restrict__ eps) {
    const float s = 1.0f + eps[0];
    int i = blockIdx.x * blockDim.x + threadIdx.x;
    const float4* x4 = reinterpret_cast<const float4*>(x);
    float4* a4 = reinterpret_cast<float4*>(g_aggr);
    if (i < M_NODES * CH / 4) {
        float4 v = x4[i];
        v.x *= s; v.y *= s; v.z *= s; v.w *= s;
        a4[i] = v;
    }
    if (blockIdx.x == 0 && threadIdx.x < CH) {
        g_sum[threadIdx.x] = 0.0f;
        g_sumsq[threadIdx.x] = 0.0f;
    }
}

// ---------------- kernel 2: scatter-add (warp per edge, red.v4) ----------------
__global__ void scatter_kernel(const float* __restrict__ x,
                               const int* __restrict__ ei32) {
    int w = (blockIdx.x * blockDim.x + threadIdx.x) >> 5;
    int lane = threadIdx.x & 31;
    if (w >= NE) return;
    const int f = g_i64flag;
    int row, col;
    if (f) {  // int64 storage: value lives in the low 32-bit word
        row = ei32[2 * (size_t)w];
        col = ei32[2 * ((size_t)NE + w)];
    } else {  // int32 storage
        row = ei32[w];
        col = ei32[NE + w];
    }
    // clamp defensively (garbage indices must never fault)
    row &= 0x7fffffff; if (row >= M_NODES) row %= M_NODES;
    col &= 0x7fffffff; if (col >= M_NODES) col %= M_NODES;
    const float4* src = reinterpret_cast<const float4*>(x + (size_t)row * CH);
    float4 v = __ldg(src + lane);
    float* dst = g_aggr + (size_t)col * CH + lane * 4;
    asm volatile("red.global.add.v4.f32 [%0], {%1,%2,%3,%4};"
                 :: "l"(dst), "f"(v.x), "f"(v.y), "f"(v.z), "f"(v.w) : "memory");
}

// ---------------- GEMM: out[m][n] = sum_k A[m][k] * W[n][k] + bias[n] ----------------
// MODE 0: A = g_aggr, out = g_h, accumulate BN statistics
// MODE 1: A = relu(g_h * scale + shift), out = d_out
// Tile: 64 rows x 128 cols, 256 threads, thread = 4 rows x 4 col-pairs (f32x2)
#define SMEM_FLOATS (64 * 132 + 128 * 130 + 256)
#define SMEM_BYTES  (SMEM_FLOATS * 4)

template <int MODE>
__global__ __launch_bounds__(256)
void gemm_kernel(const float* __restrict__ Wg, const float* __restrict__ bias,
                 float* __restrict__ outp) {
    extern __shared__ float smem[];
    float* sA    = smem;                 // [64][132] padded
    float* sW    = smem + 64 * 132;      // [128][130]: sW[k*130+n] = W[n][k]
    float* sStat = sW + 128 * 130;       // [256]: sum(0..127), sumsq(128..255)

    const int tid = threadIdx.x;
    const int tm = tid >> 4;             // 0..15 (row group)
    const int tn = tid & 15;             // 0..15 (col group)
    const int blockRow = blockIdx.x * 64;

    // load W transposed into shared (coalesced gmem reads)
    #pragma unroll
    for (int i = 0; i < 64; ++i) {
        int idx = tid + i * 256;
        int n = idx >> 7, k = idx & 127;
        sW[k * 130 + n] = Wg[idx];
    }
    // load A tile (float4), apply BN+ReLU for MODE 1
    #pragma unroll
    for (int f = tid; f < 64 * 32; f += 256) {
        int r = f >> 5, c4 = f & 31;
        int grow = blockRow + r;
        float4 v = make_float4(0.f, 0.f, 0.f, 0.f);
        if (grow < M_NODES) {
            const float* Ain = (MODE == 0) ? g_aggr : g_h;
            v = *reinterpret_cast<const float4*>(Ain + (size_t)grow * CH + c4 * 4);
            if (MODE == 1) {
                int k0 = c4 * 4;
                v.x = fmaxf(fmaf(v.x, g_scale[k0 + 0], g_shift[k0 + 0]), 0.f);
                v.y = fmaxf(fmaf(v.y, g_scale[k0 + 1], g_shift[k0 + 1]), 0.f);
                v.z = fmaxf(fmaf(v.z, g_scale[k0 + 2], g_shift[k0 + 2]), 0.f);
                v.w = fmaxf(fmaf(v.w, g_scale[k0 + 3], g_shift[k0 + 3]), 0.f);
            }
        }
        *reinterpret_cast<float4*>(sA + r * 132 + c4 * 4) = v;
    }
    if (MODE == 0) sStat[tid] = 0.0f;
    __syncthreads();

    // accumulators: 4 rows x 4 col-pairs; cols = tn*2 + 32*j (+0/+1)
    unsigned long long acc[4][4];
    #pragma unroll
    for (int r = 0; r < 4; ++r)
        #pragma unroll
        for (int j = 0; j < 4; ++j) acc[r][j] = 0ull;

    const unsigned long long* sW64 = reinterpret_cast<const unsigned long long*>(sW);
    const int wbase = tn;  // ull index within a k-row: k*65 + tn + 16*j

    #pragma unroll 8
    for (int k = 0; k < 128; ++k) {
        unsigned long long w0 = sW64[k * 65 + wbase + 0];
        unsigned long long w1 = sW64[k * 65 + wbase + 16];
        unsigned long long w2 = sW64[k * 65 + wbase + 32];
        unsigned long long w3 = sW64[k * 65 + wbase + 48];
        #pragma unroll
        for (int r = 0; r < 4; ++r) {
            unsigned long long a = pack2(sA[(tm * 4 + r) * 132 + k]);
            fma2(acc[r][0], a, w0);
            fma2(acc[r][1], a, w1);
            fma2(acc[r][2], a, w2);
            fma2(acc[r][3], a, w3);
        }
    }

    float* out_ptr = (MODE == 0) ? g_h : outp;
    float csum[8], csq[8];
    #pragma unroll
    for (int j = 0; j < 8; ++j) { csum[j] = 0.f; csq[j] = 0.f; }

    #pragma unroll
    for (int r = 0; r < 4; ++r) {
        int grow = blockRow + tm * 4 + r;
        if (grow >= M_NODES) continue;
        float* orow = out_ptr + (size_t)grow * CH;
        #pragma unroll
        for (int j = 0; j < 4; ++j) {
            int c = tn * 2 + 32 * j;
            float lo, hi;
            unpack2(acc[r][j], lo, hi);
            lo += __ldg(&bias[c]);
            hi += __ldg(&bias[c + 1]);
            *reinterpret_cast<float2*>(orow + c) = make_float2(lo, hi);
            if (MODE == 0) {
                csum[2 * j] += lo;     csum[2 * j + 1] += hi;
                csq[2 * j] += lo * lo; csq[2 * j + 1] += hi * hi;
            }
        }
    }

    if (MODE == 0) {
        #pragma unroll
        for (int j = 0; j < 4; ++j) {
            int c = tn * 2 + 32 * j;
            atomicAdd(&sStat[c], csum[2 * j]);
            atomicAdd(&sStat[c + 1], csum[2 * j + 1]);
            atomicAdd(&sStat[128 + c], csq[2 * j]);
            atomicAdd(&sStat[128 + c + 1], csq[2 * j + 1]);
        }
        __syncthreads();
        if (tid < CH) {
            atomicAdd(&g_sum[tid], sStat[tid]);
            atomicAdd(&g_sumsq[tid], sStat[128 + tid]);
        }
    }
}

// ---------------- kernel 4: BN finalize ----------------
__global__ void bn_finalize(const float* __restrict__ gamma,
                            const float* __restrict__ beta) {
    int c = threadIdx.x;
    float invN = 1.0f / (float)M_NODES;
    float mean = g_sum[c] * invN;
    float var = g_sumsq[c] * invN - mean * mean;
    float rs = rsqrtf(var + 1e-5f);
    float sc = gamma[c] * rs;
    g_scale[c] = sc;
    g_shift[c] = beta[c] - mean * sc;
}

// ---------------- launch ----------------
extern "C" void kernel_launch(void* const* d_in, const int* in_sizes, int n_in,
                              void* d_out, int out_size) {
    const float* x     = (const float*)d_in[0];
    const int*   ei32  = (const int*)d_in[1];
    const float* eps   = (const float*)d_in[2];
    const float* W1    = (const float*)d_in[3];
    const float* b1    = (const float*)d_in[4];
    const float* gamma = (const float*)d_in[5];
    const float* beta  = (const float*)d_in[6];
    const float* W2    = (const float*)d_in[7];
    const float* b2    = (const float*)d_in[8];
    float*       out   = (float*)d_out;

    cudaFuncSetAttribute(gemm_kernel<0>, cudaFuncAttributeMaxDynamicSharedMemorySize, SMEM_BYTES);
    cudaFuncSetAttribute(gemm_kernel<1>, cudaFuncAttributeMaxDynamicSharedMemorySize, SMEM_BYTES);

    detect_kernel<<<1, 256>>>(ei32);
    init_kernel<<<(M_NODES * CH / 4 + 255) / 256, 256>>>(x, eps);
    scatter_kernel<<<(NE * 32) / 256, 256>>>(x, ei32);
    gemm_kernel<0><<<(M_NODES + 63) / 64, 256, SMEM_BYTES>>>(W1, b1, nullptr);
    bn_finalize<<<1, 128>>>(gamma, beta);
    gemm_kernel<1><<<(M_NODES + 63) / 64, 256, SMEM_BYTES>>>(W2, b2, out);
}

// round 3
// speedup vs baseline: 1.0237x; 1.0237x over previous
#include <cuda_runtime.h>
#include <cuda_bf16.h>
#include <cstdint>

#define M_NODES 100000
#define CH      128
#define NE      1600000
#define SCAN_BLOCKS 98   // 98 * 1024 >= 100000

// ---------------- scratch (device globals: allocation-free) ----------------
__device__ __align__(16) float g_aggr[M_NODES * CH];
__device__ __align__(16) float g_h[M_NODES * CH];
__device__ float g_sum[CH];
__device__ float g_sumsq[CH];
__device__ float g_scale[CH];
__device__ float g_shift[CH];
__device__ int   g_i64flag;

__device__ int g_src32[NE];
__device__ int g_dst32[NE];
__device__ int g_cnt[M_NODES];
__device__ int g_off[M_NODES + 1];
__device__ int g_cur[M_NODES];
__device__ int g_srcs[NE];          // CSR: source ids grouped by dst
__device__ int g_blk[SCAN_BLOCKS];
__device__ int g_blkoff[SCAN_BLOCKS];

// ---------------- f32x2 helpers ----------------
__device__ __forceinline__ unsigned long long pack2(float a) {
    unsigned long long r;
    asm("mov.b64 %0, {%1,%1};" : "=l"(r) : "f"(a));
    return r;
}
__device__ __forceinline__ void fma2(unsigned long long& d, unsigned long long a,
                                     unsigned long long b) {
    asm volatile("fma.rn.f32x2 %0, %1, %2, %0;" : "+l"(d) : "l"(a), "l"(b));
}
__device__ __forceinline__ void unpack2(unsigned long long v, float& lo, float& hi) {
    asm("mov.b64 {%0,%1}, %2;" : "=f"(lo), "=f"(hi) : "l"(v));
}

// ---------------- dtype detect ----------------
__global__ void detect_kernel(const int* __restrict__ ei32) {
    __shared__ int nz;
    if (threadIdx.x == 0) nz = 0;
    __syncthreads();
    for (int i = threadIdx.x; i < 4096; i += blockDim.x)
        if (ei32[2 * i + 1] != 0) nz = 1;
    __syncthreads();
    if (threadIdx.x == 0) g_i64flag = (nz == 0) ? 1 : 0;
}

// ---------------- decode edges to int32, clamp ----------------
__global__ void decode_kernel(const int* __restrict__ ei32) {
    int e = blockIdx.x * blockDim.x + threadIdx.x;
    if (e >= NE) return;
    int row, col;
    if (g_i64flag) {
        row = ei32[2 * (size_t)e];
        col = ei32[2 * ((size_t)NE + e)];
    } else {
        row = ei32[e];
        col = ei32[NE + e];
    }
    row &= 0x7fffffff; if (row >= M_NODES) row %= M_NODES;
    col &= 0x7fffffff; if (col >= M_NODES) col %= M_NODES;
    g_src32[e] = row;
    g_dst32[e] = col;
}

// ---------------- zero counters + BN stats ----------------
__global__ void zero_kernel() {
    int i = blockIdx.x * blockDim.x + threadIdx.x;
    if (i < M_NODES) g_cnt[i] = 0;
    if (i < CH) { g_sum[i] = 0.0f; g_sumsq[i] = 0.0f; }
}

// ---------------- histogram of destinations ----------------
__global__ void hist_kernel() {
    int e = blockIdx.x * blockDim.x + threadIdx.x;
    if (e < NE) atomicAdd(&g_cnt[g_dst32[e]], 1);
}

// ---------------- scan stage 1: per-1024-chunk exclusive scan ----------------
__global__ void scan1_kernel() {
    __shared__ int sdata[256];
    int b = blockIdx.x, t = threadIdx.x;
    int base = b * 1024 + t * 4;
    int v0 = (base + 0 < M_NODES) ? g_cnt[base + 0] : 0;
    int v1 = (base + 1 < M_NODES) ? g_cnt[base + 1] : 0;
    int v2 = (base + 2 < M_NODES) ? g_cnt[base + 2] : 0;
    int v3 = (base + 3 < M_NODES) ? g_cnt[base + 3] : 0;
    int tsum = v0 + v1 + v2 + v3;
    sdata[t] = tsum;
    __syncthreads();
    for (int off = 1; off < 256; off <<= 1) {
        int val = (t >= off) ? sdata[t - off] : 0;
        __syncthreads();
        sdata[t] += val;
        __syncthreads();
    }
    int run = sdata[t] - tsum;  // exclusive prefix of this thread
    if (base + 0 < M_NODES) g_off[base + 0] = run; run += v0;
    if (base + 1 < M_NODES) g_off[base + 1] = run; run += v1;
    if (base + 2 < M_NODES) g_off[base + 2] = run; run += v2;
    if (base + 3 < M_NODES) g_off[base + 3] = run;
    if (t == 255) g_blk[b] = sdata[255];
}

// ---------------- scan stage 2: scan the 98 block totals ----------------
__global__ void scan2_kernel() {
    __shared__ int s[128];
    int t = threadIdx.x;
    int v = (t < SCAN_BLOCKS) ? g_blk[t] : 0;
    s[t] = v;
    __syncthreads();
    for (int off = 1; off < 128; off <<= 1) {
        int val = (t >= off) ? s[t - off] : 0;
        __syncthreads();
        s[t] += val;
        __syncthreads();
    }
    if (t < SCAN_BLOCKS) g_blkoff[t] = s[t] - v;
}

// ---------------- scan stage 3: add block offsets; init cursors ----------------
__global__ void scan3_kernel() {
    int i = blockIdx.x * blockDim.x + threadIdx.x;
    if (i < M_NODES) {
        int o = g_off[i] + g_blkoff[i >> 10];
        g_off[i] = o;
        g_cur[i] = o;
    }
    if (i == 0) g_off[M_NODES] = NE;
}

// ---------------- CSR fill: group src ids by destination ----------------
__global__ void fill_kernel() {
    int e = blockIdx.x * blockDim.x + threadIdx.x;
    if (e >= NE) return;
    int pos = atomicAdd(&g_cur[g_dst32[e]], 1);
    g_srcs[pos] = g_src32[e];
}

// ---------------- aggregate: warp per node ----------------
__global__ void aggregate_kernel(const float* __restrict__ x,
                                 const float* __restrict__ eps) {
    int node = (blockIdx.x * blockDim.x + threadIdx.x) >> 5;
    int lane = threadIdx.x & 31;
    if (node >= M_NODES) return;
    int off = g_off[node];
    int end = g_off[node + 1];
    const float4* x4 = reinterpret_cast<const float4*>(x);
    float s = 1.0f + eps[0];
    float4 b = x4[(size_t)node * 32 + lane];
    float4 acc = make_float4(b.x * s, b.y * s, b.z * s, b.w * s);
    int j = off;
    for (; j + 4 <= end; j += 4) {
        int s0 = g_srcs[j], s1 = g_srcs[j + 1], s2 = g_srcs[j + 2], s3 = g_srcs[j + 3];
        float4 v0 = __ldg(&x4[(size_t)s0 * 32 + lane]);
        float4 v1 = __ldg(&x4[(size_t)s1 * 32 + lane]);
        float4 v2 = __ldg(&x4[(size_t)s2 * 32 + lane]);
        float4 v3 = __ldg(&x4[(size_t)s3 * 32 + lane]);
        acc.x += (v0.x + v1.x) + (v2.x + v3.x);
        acc.y += (v0.y + v1.y) + (v2.y + v3.y);
        acc.z += (v0.z + v1.z) + (v2.z + v3.z);
        acc.w += (v0.w + v1.w) + (v2.w + v3.w);
    }
    for (; j < end; ++j) {
        float4 v = __ldg(&x4[(size_t)g_srcs[j] * 32 + lane]);
        acc.x += v.x; acc.y += v.y; acc.z += v.z; acc.w += v.w;
    }
    reinterpret_cast<float4*>(g_aggr)[(size_t)node * 32 + lane] = acc;
}

// ---------------- GEMM: out[m][n] = sum_k A[m][k]*W[n][k] + bias[n] ----------------
// Tile 64x128, 256 threads, thread = 4 rows x 4 col-pairs (f32x2).
// sW2 stores W permuted so each thread's 4 col-pairs are 8 contiguous floats:
//   pos(n) = ((n>>1)&15)*8 + (n>>5)*2 + (n&1);  row stride 136 floats.
#define SW2_STRIDE 136
#define SMEM_FLOATS (64 * 132 + 128 * SW2_STRIDE + 256)
#define SMEM_BYTES  (SMEM_FLOATS * 4)

template <int MODE>
__global__ __launch_bounds__(256)
void gemm_kernel(const float* __restrict__ Wg, const float* __restrict__ bias,
                 float* __restrict__ outp) {
    extern __shared__ float smem[];
    float* sA    = smem;                        // [64][132]
    float* sW2   = smem + 64 * 132;             // [128][136] permuted
    float* sStat = sW2 + 128 * SW2_STRIDE;      // [256]

    const int tid = threadIdx.x;
    const int tm = tid >> 4;
    const int tn = tid & 15;
    const int blockRow = blockIdx.x * 64;

    // load W permuted-transposed into shared
    #pragma unroll
    for (int i = 0; i < 64; ++i) {
        int idx = tid + i * 256;
        int n = idx >> 7, k = idx & 127;
        int pos = ((n >> 1) & 15) * 8 + (n >> 5) * 2 + (n & 1);
        sW2[k * SW2_STRIDE + pos] = Wg[idx];
    }
    // load A tile (float4), BN+ReLU for MODE 1
    #pragma unroll
    for (int f = tid; f < 64 * 32; f += 256) {
        int r = f >> 5, c4 = f & 31;
        int grow = blockRow + r;
        float4 v = make_float4(0.f, 0.f, 0.f, 0.f);
        if (grow < M_NODES) {
            const float* Ain = (MODE == 0) ? g_aggr : g_h;
            v = *reinterpret_cast<const float4*>(Ain + (size_t)grow * CH + c4 * 4);
            if (MODE == 1) {
                int k0 = c4 * 4;
                v.x = fmaxf(fmaf(v.x, g_scale[k0 + 0], g_shift[k0 + 0]), 0.f);
                v.y = fmaxf(fmaf(v.y, g_scale[k0 + 1], g_shift[k0 + 1]), 0.f);
                v.z = fmaxf(fmaf(v.z, g_scale[k0 + 2], g_shift[k0 + 2]), 0.f);
                v.w = fmaxf(fmaf(v.w, g_scale[k0 + 3], g_shift[k0 + 3]), 0.f);
            }
        }
        *reinterpret_cast<float4*>(sA + r * 132 + c4 * 4) = v;
    }
    if (MODE == 0) sStat[tid] = 0.0f;
    __syncthreads();

    unsigned long long acc[4][4];
    #pragma unroll
    for (int r = 0; r < 4; ++r)
        #pragma unroll
        for (int j = 0; j < 4; ++j) acc[r][j] = 0ull;

    #pragma unroll 2
    for (int k = 0; k < 128; k += 4) {
        float4 a0 = *reinterpret_cast<const float4*>(sA + (tm * 4 + 0) * 132 + k);
        float4 a1 = *reinterpret_cast<const float4*>(sA + (tm * 4 + 1) * 132 + k);
        float4 a2 = *reinterpret_cast<const float4*>(sA + (tm * 4 + 2) * 132 + k);
        float4 a3 = *reinterpret_cast<const float4*>(sA + (tm * 4 + 3) * 132 + k);
        #pragma unroll
        for (int kk = 0; kk < 4; ++kk) {
            const float* wp = sW2 + (k + kk) * SW2_STRIDE + tn * 8;
            ulonglong2 wA = *reinterpret_cast<const ulonglong2*>(wp);
            ulonglong2 wB = *reinterpret_cast<const ulonglong2*>(wp + 4);
            float av0 = (kk == 0) ? a0.x : (kk == 1) ? a0.y : (kk == 2) ? a0.z : a0.w;
            float av1 = (kk == 0) ? a1.x : (kk == 1) ? a1.y : (kk == 2) ? a1.z : a1.w;
            float av2 = (kk == 0) ? a2.x : (kk == 1) ? a2.y : (kk == 2) ? a2.z : a2.w;
            float av3 = (kk == 0) ? a3.x : (kk == 1) ? a3.y : (kk == 2) ? a3.z : a3.w;
            unsigned long long p0 = pack2(av0), p1 = pack2(av1);
            unsigned long long p2 = pack2(av2), p3 = pack2(av3);
            fma2(acc[0][0], p0, wA.x); fma2(acc[0][1], p0, wA.y);
            fma2(acc[0][2], p0, wB.x); fma2(acc[0][3], p0, wB.y);
            fma2(acc[1][0], p1, wA.x); fma2(acc[1][1], p1, wA.y);
            fma2(acc[1][2], p1, wB.x); fma2(acc[1][3], p1, wB.y);
            fma2(acc[2][0], p2, wA.x); fma2(acc[2][1], p2, wA.y);
            fma2(acc[2][2], p2, wB.x); fma2(acc[2][3], p2, wB.y);
            fma2(acc[3][0], p3, wA.x); fma2(acc[3][1], p3, wA.y);
            fma2(acc[3][2], p3, wB.x); fma2(acc[3][3], p3, wB.y);
        }
    }

    float* out_ptr = (MODE == 0) ? g_h : outp;
    float csum[8], csq[8];
    #pragma unroll
    for (int j = 0; j < 8; ++j) { csum[j] = 0.f; csq[j] = 0.f; }

    #pragma unroll
    for (int r = 0; r < 4; ++r) {
        int grow = blockRow + tm * 4 + r;
        if (grow >= M_NODES) continue;
        float* orow = out_ptr + (size_t)grow * CH;
        #pragma unroll
        for (int j = 0; j < 4; ++j) {
            int c = tn * 2 + 32 * j;
            float lo, hi;
            unpack2(acc[r][j], lo, hi);
            lo += __ldg(&bias[c]);
            hi += __ldg(&bias[c + 1]);
            *reinterpret_cast<float2*>(orow + c) = make_float2(lo, hi);
            if (MODE == 0) {
                csum[2 * j] += lo;     csum[2 * j + 1] += hi;
                csq[2 * j] += lo * lo; csq[2 * j + 1] += hi * hi;
            }
        }
    }

    if (MODE == 0) {
        #pragma unroll
        for (int j = 0; j < 4; ++j) {
            int c = tn * 2 + 32 * j;
            atomicAdd(&sStat[c], csum[2 * j]);
            atomicAdd(&sStat[c + 1], csum[2 * j + 1]);
            atomicAdd(&sStat[128 + c], csq[2 * j]);
            atomicAdd(&sStat[128 + c + 1], csq[2 * j + 1]);
        }
        __syncthreads();
        if (tid < CH) {
            atomicAdd(&g_sum[tid], sStat[tid]);
            atomicAdd(&g_sumsq[tid], sStat[128 + tid]);
        }
    }
}

// ---------------- BN finalize ----------------
__global__ void bn_finalize(const float* __restrict__ gamma,
                            const float* __restrict__ beta) {
    int c = threadIdx.x;
    float invN = 1.0f / (float)M_NODES;
    float mean = g_sum[c] * invN;
    float var = g_sumsq[c] * invN - mean * mean;
    float rs = rsqrtf(var + 1e-5f);
    float sc = gamma[c] * rs;
    g_scale[c] = sc;
    g_shift[c] = beta[c] - mean * sc;
}

// ---------------- launch ----------------
extern "C" void kernel_launch(void* const* d_in, const int* in_sizes, int n_in,
                              void* d_out, int out_size) {
    const float* x     = (const float*)d_in[0];
    const int*   ei32  = (const int*)d_in[1];
    const float* eps   = (const float*)d_in[2];
    const float* W1    = (const float*)d_in[3];
    const float* b1    = (const float*)d_in[4];
    const float* gamma = (const float*)d_in[5];
    const float* beta  = (const float*)d_in[6];
    const float* W2    = (const float*)d_in[7];
    const float* b2    = (const float*)d_in[8];
    float*       out   = (float*)d_out;

    cudaFuncSetAttribute(gemm_kernel<0>, cudaFuncAttributeMaxDynamicSharedMemorySize, SMEM_BYTES);
    cudaFuncSetAttribute(gemm_kernel<1>, cudaFuncAttributeMaxDynamicSharedMemorySize, SMEM_BYTES);

    detect_kernel<<<1, 256>>>(ei32);
    decode_kernel<<<(NE + 255) / 256, 256>>>(ei32);
    zero_kernel<<<(M_NODES + 255) / 256, 256>>>();
    hist_kernel<<<(NE + 255) / 256, 256>>>();
    scan1_kernel<<<SCAN_BLOCKS, 256>>>();
    scan2_kernel<<<1, 128>>>();
    scan3_kernel<<<(M_NODES + 255) / 256, 256>>>();
    fill_kernel<<<(NE + 255) / 256, 256>>>();
    aggregate_kernel<<<(M_NODES * 32 + 255) / 256, 256>>>(x, eps);
    gemm_kernel<0><<<(M_NODES + 63) / 64, 256, SMEM_BYTES>>>(W1, b1, nullptr);
    bn_finalize<<<1, 128>>>(gamma, beta);
    gemm_kernel<1><<<(M_NODES + 63) / 64, 256, SMEM_BYTES>>>(W2, b2, out);
}

// round 5
// speedup vs baseline: 1.8961x; 1.8522x over previous
#include <cuda_runtime.h>
#include <cuda_bf16.h>
#include <cstdint>

#define M_NODES 100000
#define CH      128
#define NE      1600000
#define SCAN_BLOCKS 98
#define TILE_M  128
#define GEMM_GRID ((M_NODES + TILE_M - 1) / TILE_M)

// ---------------- scratch ----------------
__device__ __align__(16) float g_aggr[M_NODES * CH];
__device__ __align__(16) float g_h[M_NODES * CH];
__device__ float g_sum[CH];
__device__ float g_sumsq[CH];
__device__ float g_scale[CH];
__device__ float g_shift[CH];
__device__ int   g_i64flag;

__device__ int g_src32[NE];
__device__ int g_dst32[NE];
__device__ int g_cnt[M_NODES];
__device__ int g_off[M_NODES + 1];
__device__ int g_cur[M_NODES];
__device__ int g_srcs[NE];
__device__ int g_blk[SCAN_BLOCKS];
__device__ int g_blkoff[SCAN_BLOCKS];

// pre-split weights, plain row-major [n][k]: [0]=W1, [1]=W2
__device__ __align__(16) unsigned short g_whi[2][CH * CH];
__device__ __align__(16) unsigned short g_wlo[2][CH * CH];

// ---------------- helpers ----------------
__device__ __forceinline__ uint32_t packbf2(float lo, float hi) {
    uint32_t r;  // first PTX src -> upper half
    asm("cvt.rn.bf16x2.f32 %0, %1, %2;" : "=r"(r) : "f"(hi), "f"(lo));
    return r;
}
// split float2 -> bf16x2 hi + bf16x2 lo (residual)
__device__ __forceinline__ void split2(float2 v, uint32_t& hi, uint32_t& lo) {
    uint32_t h = packbf2(v.x, v.y);
    float hx = __uint_as_float(h << 16);
    float hy = __uint_as_float(h & 0xffff0000u);
    lo = packbf2(v.x - hx, v.y - hy);
    hi = h;
}
__device__ __forceinline__ void mma16816(float* c, uint32_t a0, uint32_t a1,
                                         uint32_t a2, uint32_t a3,
                                         uint32_t b0, uint32_t b1) {
    asm volatile(
        "mma.sync.aligned.m16n8k16.row.col.f32.bf16.bf16.f32 "
        "{%0,%1,%2,%3}, {%4,%5,%6,%7}, {%8,%9}, {%0,%1,%2,%3};"
        : "+f"(c[0]), "+f"(c[1]), "+f"(c[2]), "+f"(c[3])
        : "r"(a0), "r"(a1), "r"(a2), "r"(a3), "r"(b0), "r"(b1));
}

// ---------------- W prep: split fp32 -> bf16 hi/lo, row-major ----------------
__global__ void prep_w(const float* __restrict__ W1, const float* __restrict__ W2) {
    const float* W = (blockIdx.x == 0) ? W1 : W2;
    unsigned short* hi = g_whi[blockIdx.x];
    unsigned short* lo = g_wlo[blockIdx.x];
    for (int i = threadIdx.x; i < CH * CH; i += blockDim.x) {
        float w = W[i];
        __nv_bfloat16 bh = __float2bfloat16(w);
        float hf = __bfloat162float(bh);
        hi[i] = __bfloat16_as_ushort(bh);
        lo[i] = __bfloat16_as_ushort(__float2bfloat16(w - hf));
    }
}

// ---------------- dtype detect ----------------
__global__ void detect_kernel(const int* __restrict__ ei32) {
    __shared__ int nz;
    if (threadIdx.x == 0) nz = 0;
    __syncthreads();
    for (int i = threadIdx.x; i < 4096; i += blockDim.x)
        if (ei32[2 * i + 1] != 0) nz = 1;
    __syncthreads();
    if (threadIdx.x == 0) g_i64flag = (nz == 0) ? 1 : 0;
}

// ---------------- zero counters + BN stats ----------------
__global__ void zero_kernel() {
    int i = blockIdx.x * blockDim.x + threadIdx.x;
    if (i < M_NODES) g_cnt[i] = 0;
    if (i < CH) { g_sum[i] = 0.0f; g_sumsq[i] = 0.0f; }
}

// ---------------- decode + histogram ----------------
__global__ void decode_hist(const int* __restrict__ ei32) {
    int e = blockIdx.x * blockDim.x + threadIdx.x;
    if (e >= NE) return;
    int row, col;
    if (g_i64flag) {
        row = ei32[2 * (size_t)e];
        col = ei32[2 * ((size_t)NE + e)];
    } else {
        row = ei32[e];
        col = ei32[NE + e];
    }
    row &= 0x7fffffff; if (row >= M_NODES) row %= M_NODES;
    col &= 0x7fffffff; if (col >= M_NODES) col %= M_NODES;
    g_src32[e] = row;
    g_dst32[e] = col;
    atomicAdd(&g_cnt[col], 1);
}

// ---------------- scans ----------------
__global__ void scan1_kernel() {
    __shared__ int sdata[256];
    int b = blockIdx.x, t = threadIdx.x;
    int base = b * 1024 + t * 4;
    int v0 = (base + 0 < M_NODES) ? g_cnt[base + 0] : 0;
    int v1 = (base + 1 < M_NODES) ? g_cnt[base + 1] : 0;
    int v2 = (base + 2 < M_NODES) ? g_cnt[base + 2] : 0;
    int v3 = (base + 3 < M_NODES) ? g_cnt[base + 3] : 0;
    int tsum = v0 + v1 + v2 + v3;
    sdata[t] = tsum;
    __syncthreads();
    for (int off = 1; off < 256; off <<= 1) {
        int val = (t >= off) ? sdata[t - off] : 0;
        __syncthreads();
        sdata[t] += val;
        __syncthreads();
    }
    int run = sdata[t] - tsum;
    if (base + 0 < M_NODES) g_off[base + 0] = run; run += v0;
    if (base + 1 < M_NODES) g_off[base + 1] = run; run += v1;
    if (base + 2 < M_NODES) g_off[base + 2] = run; run += v2;
    if (base + 3 < M_NODES) g_off[base + 3] = run;
    if (t == 255) g_blk[b] = sdata[255];
}
__global__ void scan2_kernel() {
    __shared__ int s[128];
    int t = threadIdx.x;
    int v = (t < SCAN_BLOCKS) ? g_blk[t] : 0;
    s[t] = v;
    __syncthreads();
    for (int off = 1; off < 128; off <<= 1) {
        int val = (t >= off) ? s[t - off] : 0;
        __syncthreads();
        s[t] += val;
        __syncthreads();
    }
    if (t < SCAN_BLOCKS) g_blkoff[t] = s[t] - v;
}
__global__ void scan3_kernel() {
    int i = blockIdx.x * blockDim.x + threadIdx.x;
    if (i < M_NODES) {
        int o = g_off[i] + g_blkoff[i >> 10];
        g_off[i] = o;
        g_cur[i] = o;
    }
    if (i == 0) g_off[M_NODES] = NE;
}
__global__ void fill_kernel() {
    int e = blockIdx.x * blockDim.x + threadIdx.x;
    if (e >= NE) return;
    int pos = atomicAdd(&g_cur[g_dst32[e]], 1);
    g_srcs[pos] = g_src32[e];
}

// ---------------- aggregate: warp per node ----------------
__global__ void aggregate_kernel(const float* __restrict__ x,
                                 const float* __restrict__ eps) {
    int node = (blockIdx.x * blockDim.x + threadIdx.x) >> 5;
    int lane = threadIdx.x & 31;
    if (node >= M_NODES) return;
    int off = g_off[node];
    int end = g_off[node + 1];
    const float4* x4 = reinterpret_cast<const float4*>(x);
    float s = 1.0f + eps[0];
    float4 b = x4[(size_t)node * 32 + lane];
    float4 acc = make_float4(b.x * s, b.y * s, b.z * s, b.w * s);
    int j = off;
    for (; j + 4 <= end; j += 4) {
        int s0 = g_srcs[j], s1 = g_srcs[j + 1], s2 = g_srcs[j + 2], s3 = g_srcs[j + 3];
        float4 v0 = __ldg(&x4[(size_t)s0 * 32 + lane]);
        float4 v1 = __ldg(&x4[(size_t)s1 * 32 + lane]);
        float4 v2 = __ldg(&x4[(size_t)s2 * 32 + lane]);
        float4 v3 = __ldg(&x4[(size_t)s3 * 32 + lane]);
        acc.x += (v0.x + v1.x) + (v2.x + v3.x);
        acc.y += (v0.y + v1.y) + (v2.y + v3.y);
        acc.z += (v0.z + v1.z) + (v2.z + v3.z);
        acc.w += (v0.w + v1.w) + (v2.w + v3.w);
    }
    for (; j < end; ++j) {
        float4 v = __ldg(&x4[(size_t)g_srcs[j] * 32 + lane]);
        acc.x += v.x; acc.y += v.y; acc.z += v.z; acc.w += v.w;
    }
    reinterpret_cast<float4*>(g_aggr)[(size_t)node * 32 + lane] = acc;
}

// ---------------- mma.sync GEMM ----------------
// out[m][n] = sum_k A[m][k] * W[n][k] + bias[n]
// MODE 0: A = g_aggr -> g_h, + BN stats.  MODE 1: A = relu(g_h*scale+shift) -> outp.
// Block: 128x128 tile, 8 warps (4 m x 2 n), warp tile 32x64.
#define WSTRIDE 132
#define SM_WHI   0
#define SM_WLO   (128 * WSTRIDE * 2)
#define SM_BIAS  (2 * 128 * WSTRIDE * 2)
#define SM_SCALE (SM_BIAS + 512)
#define SM_SHIFT (SM_SCALE + 512)
#define SM_STAT  (SM_SHIFT + 512)
#define SMEM_TOTAL (SM_STAT + 1024)

template <int MODE>
__global__ __launch_bounds__(256)
void mma_gemm(const float* __restrict__ bias, float* __restrict__ outp) {
    extern __shared__ char smem[];
    unsigned short* sWhi = reinterpret_cast<unsigned short*>(smem + SM_WHI);
    unsigned short* sWlo = reinterpret_cast<unsigned short*>(smem + SM_WLO);
    float* sBias  = reinterpret_cast<float*>(smem + SM_BIAS);
    float* sScale = reinterpret_cast<float*>(smem + SM_SCALE);
    float* sShift = reinterpret_cast<float*>(smem + SM_SHIFT);
    float* sStat  = reinterpret_cast<float*>(smem + SM_STAT);

    const int tid  = threadIdx.x;
    const int wid  = tid >> 5;
    const int lane = tid & 31;
    const int wm   = wid & 3;        // 0..3 (m)
    const int wn   = wid >> 2;       // 0..1 (n)
    const int g    = lane >> 2;      // 0..7
    const int t    = lane & 3;       // 0..3
    const int blockRow = blockIdx.x * TILE_M;

    // stage W hi/lo into padded smem (uint2 = 4 bf16)
    {
        const uint2* sh = reinterpret_cast<const uint2*>(g_whi[MODE]);
        const uint2* sl = reinterpret_cast<const uint2*>(g_wlo[MODE]);
        #pragma unroll
        for (int i = tid; i < 4096; i += 256) {
            int n = i >> 5, m = i & 31;
            *reinterpret_cast<uint2*>(sWhi + n * WSTRIDE + m * 4) = sh[i];
            *reinterpret_cast<uint2*>(sWlo + n * WSTRIDE + m * 4) = sl[i];
        }
    }
    if (tid < 128) {
        sBias[tid] = bias[tid];
        if (MODE == 1) { sScale[tid] = g_scale[tid]; sShift[tid] = g_shift[tid]; }
    }
    if (MODE == 0 && tid < 256) sStat[tid] = 0.0f;
    __syncthreads();

    // A row pointers (clamped; validity flags for store/stats)
    const float* Ag = (MODE == 0) ? g_aggr : g_h;
    int r0 = blockRow + wm * 32 + g;          // mt=0 rows g / g+8
    int r1 = r0 + 16;                          // mt=1
    bool v00 = r0 < M_NODES,      v01 = (r0 + 8) < M_NODES;
    bool v10 = r1 < M_NODES,      v11 = (r1 + 8) < M_NODES;
    const float* rp00 = Ag + (size_t)(v00 ? r0 : 0) * CH;
    const float* rp01 = Ag + (size_t)(v01 ? r0 + 8 : 0) * CH;
    const float* rp10 = Ag + (size_t)(v10 ? r1 : 0) * CH;
    const float* rp11 = Ag + (size_t)(v11 ? r1 + 8 : 0) * CH;

    float acc[2][8][4];
    #pragma unroll
    for (int mt = 0; mt < 2; ++mt)
        #pragma unroll
        for (int nt = 0; nt < 8; ++nt)
            #pragma unroll
            for (int i = 0; i < 4; ++i) acc[mt][nt][i] = 0.0f;

    #pragma unroll 2
    for (int ks = 0; ks < 8; ++ks) {
        const int k0 = ks * 16;
        const int ca = k0 + 2 * t;       // cols for a0/a1
        const int cb = ca + 8;           // cols for a2/a3

        uint32_t ahi[2][4], alo[2][4];
        const float* rps[2][2] = {{rp00, rp01}, {rp10, rp11}};
        #pragma unroll
        for (int mt = 0; mt < 2; ++mt) {
            float2 x0 = *reinterpret_cast<const float2*>(rps[mt][0] + ca);
            float2 x2 = *reinterpret_cast<const float2*>(rps[mt][0] + cb);
            float2 x1 = *reinterpret_cast<const float2*>(rps[mt][1] + ca);
            float2 x3 = *reinterpret_cast<const float2*>(rps[mt][1] + cb);
            if (MODE == 1) {
                float2 scA = *reinterpret_cast<const float2*>(sScale + ca);
                float2 shA = *reinterpret_cast<const float2*>(sShift + ca);
                float2 scB = *reinterpret_cast<const float2*>(sScale + cb);
                float2 shB = *reinterpret_cast<const float2*>(sShift + cb);
                x0.x = fmaxf(fmaf(x0.x, scA.x, shA.x), 0.f);
                x0.y = fmaxf(fmaf(x0.y, scA.y, shA.y), 0.f);
                x1.x = fmaxf(fmaf(x1.x, scA.x, shA.x), 0.f);
                x1.y = fmaxf(fmaf(x1.y, scA.y, shA.y), 0.f);
                x2.x = fmaxf(fmaf(x2.x, scB.x, shB.x), 0.f);
                x2.y = fmaxf(fmaf(x2.y, scB.y, shB.y), 0.f);
                x3.x = fmaxf(fmaf(x3.x, scB.x, shB.x), 0.f);
                x3.y = fmaxf(fmaf(x3.y, scB.y, shB.y), 0.f);
            }
            split2(x0, ahi[mt][0], alo[mt][0]);
            split2(x1, ahi[mt][1], alo[mt][1]);
            split2(x2, ahi[mt][2], alo[mt][2]);
            split2(x3, ahi[mt][3], alo[mt][3]);
        }

        uint32_t bhi[8][2], blo[8][2];
        #pragma unroll
        for (int nt = 0; nt < 8; ++nt) {
            int n = wn * 64 + nt * 8 + g;
            const unsigned short* ph = sWhi + n * WSTRIDE;
            const unsigned short* pl = sWlo + n * WSTRIDE;
            bhi[nt][0] = *reinterpret_cast<const uint32_t*>(ph + ca);
            bhi[nt][1] = *reinterpret_cast<const uint32_t*>(ph + cb);
            blo[nt][0] = *reinterpret_cast<const uint32_t*>(pl + ca);
            blo[nt][1] = *reinterpret_cast<const uint32_t*>(pl + cb);
        }

        #pragma unroll
        for (int mt = 0; mt < 2; ++mt)
            #pragma unroll
            for (int nt = 0; nt < 8; ++nt) {
                mma16816(acc[mt][nt], ahi[mt][0], ahi[mt][1], ahi[mt][2], ahi[mt][3],
                         bhi[nt][0], bhi[nt][1]);
                mma16816(acc[mt][nt], ahi[mt][0], ahi[mt][1], ahi[mt][2], ahi[mt][3],
                         blo[nt][0], blo[nt][1]);
                mma16816(acc[mt][nt], alo[mt][0], alo[mt][1], alo[mt][2], alo[mt][3],
                         bhi[nt][0], bhi[nt][1]);
            }
    }

    // ---- epilogue ----
    float* obase = (MODE == 0) ? g_h : outp;
    float cs[8][2], cq[8][2];
    if (MODE == 0) {
        #pragma unroll
        for (int nt = 0; nt < 8; ++nt) {
            cs[nt][0] = cs[nt][1] = 0.f;
            cq[nt][0] = cq[nt][1] = 0.f;
        }
    }
    const bool vrow[2][2] = {{v00, v01}, {v10, v11}};
    const int  rrow[2][2] = {{r0, r0 + 8}, {r1, r1 + 8}};
    #pragma unroll
    for (int mt = 0; mt < 2; ++mt) {
        #pragma unroll
        for (int nt = 0; nt < 8; ++nt) {
            int c = wn * 64 + nt * 8 + 2 * t;
            float b0 = sBias[c], b1 = sBias[c + 1];
            float o00 = acc[mt][nt][0] + b0, o01 = acc[mt][nt][1] + b1;  // row g
            float o10 = acc[mt][nt][2] + b0, o11 = acc[mt][nt][3] + b1;  // row g+8
            if (vrow[mt][0])
                *reinterpret_cast<float2*>(obase + (size_t)rrow[mt][0] * CH + c) =
                    make_float2(o00, o01);
            if (vrow[mt][1])
                *reinterpret_cast<float2*>(obase + (size_t)rrow[mt][1] * CH + c) =
                    make_float2(o10, o11);
            if (MODE == 0) {
                float m00 = vrow[mt][0] ? o00 : 0.f, m01 = vrow[mt][0] ? o01 : 0.f;
                float m10 = vrow[mt][1] ? o10 : 0.f, m11 = vrow[mt][1] ? o11 : 0.f;
                cs[nt][0] += m00 + m10;
                cs[nt][1] += m01 + m11;
                cq[nt][0] += m00 * m00 + m10 * m10;
                cq[nt][1] += m01 * m01 + m11 * m11;
            }
        }
    }
    if (MODE == 0) {
        #pragma unroll
        for (int nt = 0; nt < 8; ++nt) {
            float s0 = cs[nt][0], s1 = cs[nt][1], q0 = cq[nt][0], q1 = cq[nt][1];
            #pragma unroll
            for (int off = 4; off < 32; off <<= 1) {
                s0 += __shfl_xor_sync(0xffffffffu, s0, off);
                s1 += __shfl_xor_sync(0xffffffffu, s1, off);
                q0 += __shfl_xor_sync(0xffffffffu, q0, off);
                q1 += __shfl_xor_sync(0xffffffffu, q1, off);
            }
            if (lane < 4) {
                int c = wn * 64 + nt * 8 + 2 * t;
                atomicAdd(&sStat[c], s0);
                atomicAdd(&sStat[c + 1], s1);
                atomicAdd(&sStat[128 + c], q0);
                atomicAdd(&sStat[128 + c + 1], q1);
            }
        }
        __syncthreads();
        if (tid < 128) atomicAdd(&g_sum[tid], sStat[tid]);
        else           atomicAdd(&g_sumsq[tid - 128], sStat[tid]);
    }
}

// ---------------- BN finalize ----------------
__global__ void bn_finalize(const float* __restrict__ gamma,
                            const float* __restrict__ beta) {
    int c = threadIdx.x;
    float invN = 1.0f / (float)M_NODES;
    float mean = g_sum[c] * invN;
    float var = g_sumsq[c] * invN - mean * mean;
    float rs = rsqrtf(var + 1e-5f);
    float sc = gamma[c] * rs;
    g_scale[c] = sc;
    g_shift[c] = beta[c] - mean * sc;
}

// ---------------- launch ----------------
extern "C" void kernel_launch(void* const* d_in, const int* in_sizes, int n_in,
                              void* d_out, int out_size) {
    const float* x     = (const float*)d_in[0];
    const int*   ei32  = (const int*)d_in[1];
    const float* eps   = (const float*)d_in[2];
    const float* W1    = (const float*)d_in[3];
    const float* b1    = (const float*)d_in[4];
    const float* gamma = (const float*)d_in[5];
    const float* beta  = (const float*)d_in[6];
    const float* W2    = (const float*)d_in[7];
    const float* b2    = (const float*)d_in[8];
    float*       out   = (float*)d_out;

    cudaFuncSetAttribute(mma_gemm<0>, cudaFuncAttributeMaxDynamicSharedMemorySize, SMEM_TOTAL);
    cudaFuncSetAttribute(mma_gemm<1>, cudaFuncAttributeMaxDynamicSharedMemorySize, SMEM_TOTAL);

    prep_w<<<2, 256>>>(W1, W2);
    detect_kernel<<<1, 256>>>(ei32);
    zero_kernel<<<(M_NODES + 255) / 256, 256>>>();
    decode_hist<<<(NE + 255) / 256, 256>>>(ei32);
    scan1_kernel<<<SCAN_BLOCKS, 256>>>();
    scan2_kernel<<<1, 128>>>();
    scan3_kernel<<<(M_NODES + 255) / 256, 256>>>();
    fill_kernel<<<(NE + 255) / 256, 256>>>();
    aggregate_kernel<<<(M_NODES * 32 + 255) / 256, 256>>>(x, eps);
    mma_gemm<0><<<GEMM_GRID, 256, SMEM_TOTAL>>>(b1, nullptr);
    bn_finalize<<<1, 128>>>(gamma, beta);
    mma_gemm<1><<<GEMM_GRID, 256, SMEM_TOTAL>>>(b2, out);
}